// round 5
// baseline (speedup 1.0000x reference)
#include <cuda_runtime.h>
#include <cstdint>

// Idx2PixelLayer: bilinear gather of N=1e6 points from a 2048x2048x8 fp32 image.
// c = ((coord - 1) mod (dim - 4)) + 1   (non-negative mod, JAX semantics)
// out = w00*g(0,0) + w10*g(1,0) + w01*g(0,1) + w11*g(1,1)
//   w00=d0*d1, w10=(1-d0)*d1, w01=d0*(1-d1), w11=(1-d0)*(1-d1)
// Reference's off-mask is always false (c <= 2045 < 2048), so dropped.
//
// Layout: 2 threads per point; thread half k (=tid&1) handles channels 4k..4k+3,
// so lane pairs cover one 32B pixel sector per gather (1 L1tex wavefront/point/gather).
//
// Cache policy: image gathers carry an L2::evict_last cache-hint policy
// (createpolicy + ld.global.nc.L2::cache_hint — the bare evict_last modifier
// only accepts 256-bit loads on sm_103). Goal: keep the ~100MB unique image
// hot set resident in the ~126MB L2 across graph replays (L2 persists; only
// L1 flushes per launch). Coords are evict-first loads, output evict-first
// stores, so 40MB/launch of streaming traffic can't thrash the pinned lines.

static constexpr int H = 2048;
static constexpr int W = 2048;
static constexpr int C = 8;

__device__ __forceinline__ uint64_t make_evict_last_policy() {
    uint64_t pol;
    asm("createpolicy.fractional.L2::evict_last.b64 %0, 1.0;" : "=l"(pol));
    return pol;
}

__device__ __forceinline__ float4 ldg_hint_f4(const float4* p, uint64_t pol) {
    float4 v;
    asm volatile("ld.global.nc.L2::cache_hint.v4.f32 {%0,%1,%2,%3}, [%4], %5;"
                 : "=f"(v.x), "=f"(v.y), "=f"(v.z), "=f"(v.w)
                 : "l"(p), "l"(pol));
    return v;
}

__global__ __launch_bounds__(256)
void idx2pixel_kernel(const float* __restrict__ coords,
                      const float* __restrict__ visible,
                      float* __restrict__ out,
                      int n)  // n = number of points
{
    int t = blockIdx.x * blockDim.x + threadIdx.x;
    int p = t >> 1;          // point index
    int k = t & 1;           // channel half: floats [4k, 4k+4)
    if (p >= n) return;

    uint64_t pol = make_evict_last_policy();

    // Both lanes of a pair read the same float2 (broadcast; streaming hint).
    float2 xy = __ldcs(reinterpret_cast<const float2*>(coords) + p);

    const float m0 = (float)(H - 4);   // 2044
    const float m1 = (float)(W - 4);

    float c0 = fmodf(xy.x - 1.0f, m0); if (c0 < 0.0f) c0 += m0; c0 += 1.0f;
    float c1 = fmodf(xy.y - 1.0f, m1); if (c1 < 0.0f) c1 += m1; c1 += 1.0f;

    float f0 = floorf(c0);
    float f1 = floorf(c1);
    float d0 = c0 - f0;
    float d1 = c1 - f1;
    int   i0 = (int)f0;
    int   i1 = (int)f1;

    // base in floats: pixel (i0,i1), + channel-half offset 4k
    int base = (i0 * W + i1) * C + 4 * k;

    const float4* p00 = reinterpret_cast<const float4*>(visible + base);             // g(0,0)
    const float4* p01 = reinterpret_cast<const float4*>(visible + base + C);         // g(0,1)
    const float4* p10 = reinterpret_cast<const float4*>(visible + base + W * C);     // g(1,0)
    const float4* p11 = reinterpret_cast<const float4*>(visible + base + W * C + C); // g(1,1)

    // Front-batch the 4 gathers for MLP; pin image lines in L2 via policy.
    float4 a00 = ldg_hint_f4(p00, pol);
    float4 a01 = ldg_hint_f4(p01, pol);
    float4 a10 = ldg_hint_f4(p10, pol);
    float4 a11 = ldg_hint_f4(p11, pol);

    float w00 = d0 * d1;
    float w10 = (1.0f - d0) * d1;
    float w01 = d0 * (1.0f - d1);
    float w11 = (1.0f - d0) * (1.0f - d1);

    float4 o;
    o.x = w00 * a00.x + w10 * a10.x + w01 * a01.x + w11 * a11.x;
    o.y = w00 * a00.y + w10 * a10.y + w01 * a01.y + w11 * a11.y;
    o.z = w00 * a00.z + w10 * a10.z + w01 * a01.z + w11 * a11.z;
    o.w = w00 * a00.w + w10 * a10.w + w01 * a01.w + w11 * a11.w;

    // Consecutive lanes write consecutive float4s — fully coalesced; streaming store.
    __stcs(reinterpret_cast<float4*>(out + p * C + 4 * k), o);
}

extern "C" void kernel_launch(void* const* d_in, const int* in_sizes, int n_in,
                              void* d_out, int out_size)
{
    const float* coords  = (const float*)d_in[0];  // [N, 2] fp32
    const float* visible = (const float*)d_in[1];  // [H, W, C] fp32
    float* out = (float*)d_out;                    // [N, C] fp32

    int n = in_sizes[0] / 2;   // number of points
    (void)n_in; (void)out_size;

    int threads = 256;
    int total = 2 * n;         // 2 threads per point
    int blocks = (total + threads - 1) / threads;
    idx2pixel_kernel<<<blocks, threads>>>(coords, visible, out, n);
}